// round 11
// baseline (speedup 1.0000x reference)
#include <cuda_runtime.h>
#include <math.h>

#define ND   20000
#define NP_  10000
#define NB   4096
#define DE   320000
#define PE   160000
#define FEAT 3372
#define HID  1024

// ---------------- static device scratch (no allocations allowed) ----------------
__device__ float g_h_d[(size_t)ND * HID];     // d GCN pre-aggregation (X @ W)
__device__ float g_h_p[(size_t)NP_ * HID];    // p GCN pre-aggregation
__device__ float g_agg_d[(size_t)ND * HID];   // d GCN aggregated output (pre-bias)
__device__ float g_agg_p[(size_t)NP_ * HID];  // p GCN aggregated output
__device__ float g_dinv_d[ND];                // degree accumulator, then rsqrt(deg+1)
__device__ float g_dinv_p[NP_];
__device__ int   g_need_d[ND];                // which output nodes are consumed
__device__ int   g_need_p[NP_];
__device__ float g_t1[(size_t)NB * HID];      // enc hidden
__device__ float g_t2[(size_t)NB * HID];      // dec hidden
__device__ float g_hbn[(size_t)NB * 128];     // BN'd pre-activation of out head
__device__ float g_bns[128];                  // folded BN scale
__device__ float g_bnb[128];                  // folded BN bias

// ---------------- small kernels ----------------

__global__ void flag_kernel(const int* __restrict__ di, const int* __restrict__ pi) {
    int i = blockIdx.x * blockDim.x + threadIdx.x;
    if (i < NB) {
        g_need_d[di[i]] = 1;
        g_need_p[pi[i]] = 1;
    }
}

__global__ void deg_kernel(const int* __restrict__ ei, const float* __restrict__ ew,
                           float* __restrict__ deg, int E) {
    int e = blockIdx.x * blockDim.x + threadIdx.x;
    if (e < E) atomicAdd(&deg[ei[E + e]], ew[e]);
}

__global__ void dinv_kernel(float* __restrict__ d, int n) {
    int i = blockIdx.x * blockDim.x + threadIdx.x;
    if (i < n) d[i] = rsqrtf(d[i] + 1.0f);   // +1 for the self loop weight
}

// out[i,:] = h[i,:] * dinv[i]^2   (self-loop term), only for needed nodes
__global__ void self_init(const float* __restrict__ h, float* __restrict__ out,
                          const float* __restrict__ dinv, const int* __restrict__ need) {
    int n = blockIdx.x;
    if (!need[n]) return;
    float s = dinv[n];
    s = s * s;
    const float4* hv = (const float4*)(h + (size_t)n * HID);
    float4* ov = (float4*)(out + (size_t)n * HID);
    float4 v = hv[threadIdx.x];
    ov[threadIdx.x] = make_float4(v.x * s, v.y * s, v.z * s, v.w * s);
}

// out[col,:] += h[row,:] * (dinv[row]*ew*dinv[col]) for needed cols. One block per edge.
__global__ void edge_agg(const float* __restrict__ h, float* __restrict__ out,
                         const float* __restrict__ dinv, const int* __restrict__ need,
                         const int* __restrict__ ei, const float* __restrict__ ew, int E) {
    int e = blockIdx.x;
    int col = ei[E + e];
    if (!need[col]) return;
    int row = ei[e];
    float nrm = dinv[row] * ew[e] * dinv[col];
    float4 v = ((const float4*)(h + (size_t)row * HID))[threadIdx.x];
    float* o = out + (size_t)col * HID + threadIdx.x * 4;
    atomicAdd(o + 0, v.x * nrm);
    atomicAdd(o + 1, v.y * nrm);
    atomicAdd(o + 2, v.z * nrm);
    atomicAdd(o + 3, v.w * nrm);
}

// feature[b,:] = concat(d_vecs[b], p_emb[b], leaky(agg_d[di]+b_d), leaky(agg_p[pi]+b_p))
__global__ void feature_kernel(const int* __restrict__ di_, const int* __restrict__ pi_,
                               const float* __restrict__ dv, const float* __restrict__ pemb,
                               const float* __restrict__ db, const float* __restrict__ pb,
                               float* __restrict__ f_out) {
    int r = blockIdx.x;
    int di = di_[r], pi = pi_[r];
    float* f = f_out + (size_t)r * FEAT;
    for (int c = threadIdx.x; c < FEAT; c += blockDim.x) {
        float v;
        if (c < 300) {
            v = dv[(size_t)r * 300 + c];
        } else if (c < 1324) {
            v = pemb[(size_t)r * 1024 + (c - 300)];
        } else if (c < 2348) {
            int j = c - 1324;
            v = g_agg_d[(size_t)di * HID + j] + db[j];
            v = v > 0.f ? v : 0.01f * v;
        } else {
            int j = c - 2348;
            v = g_agg_p[(size_t)pi * HID + j] + pb[j];
            v = v > 0.f ? v : 0.01f * v;
        }
        f[c] = v;
    }
}

__global__ void bnfold_kernel(const float* __restrict__ b1, const float* __restrict__ gamma,
                              const float* __restrict__ beta, const float* __restrict__ mean,
                              const float* __restrict__ var) {
    int i = threadIdx.x;
    float s = gamma[i] * rsqrtf(var[i] + 1e-5f);
    g_bns[i] = s;
    g_bnb[i] = (b1[i] - mean[i]) * s + beta[i];
}

// y[r] = sum_f leaky(hbn[r,f]) * W2[f] + b2  — one warp per row
__global__ void y_kernel(const float* __restrict__ W2, const float* __restrict__ b2,
                         float* __restrict__ y) {
    int r = blockIdx.x * 8 + (threadIdx.x >> 5);
    int lane = threadIdx.x & 31;
    const float* h = g_hbn + (size_t)r * 128;
    float s = 0.f;
#pragma unroll
    for (int i = 0; i < 4; i++) {
        float v = h[lane + 32 * i];
        v = v > 0.f ? v : 0.01f * v;
        s += v * W2[lane + 32 * i];
    }
#pragma unroll
    for (int o = 16; o; o >>= 1) s += __shfl_xor_sync(0xffffffffu, s, o);
    if (lane == 0) y[r] = s + b2[0];
}

// ---------------- tiled SGEMM: C[M,N] = A[M,K] @ B[K,N] (+epilogue) ----------------
// EPI: 0 = plain store, 1 = +bias[c] then leaky, 2 = *scale[c] + bias[c] (no act)
template <int EPI>
__global__ __launch_bounds__(256, 2) void sgemm(
    const float* __restrict__ A, const float* __restrict__ B, float* __restrict__ C,
    int M, int N, int K, const float* __restrict__ bias, const float* __restrict__ scale) {
    __shared__ float As[8][128];   // transposed: As[k][m]
    __shared__ float Bs[8][128];   // Bs[k][n]

    int tid = threadIdx.x;
    int bm = blockIdx.y * 128, bn = blockIdx.x * 128;
    int ty = tid >> 4, tx = tid & 15;

    float acc[8][8];
#pragma unroll
    for (int i = 0; i < 8; i++)
#pragma unroll
        for (int j = 0; j < 8; j++) acc[i][j] = 0.f;

    int a_row = tid >> 1;          // 0..127
    int a_col = (tid & 1) * 4;     // 0 or 4
    int b_row = tid >> 5;          // 0..7
    int b_col = (tid & 31) * 4;    // 0..124

    for (int k0 = 0; k0 < K; k0 += 8) {
        // A tile: 128 rows x 8 k, scalar guarded loads, store transposed
        int gr = bm + a_row;
#pragma unroll
        for (int i = 0; i < 4; i++) {
            int gk = k0 + a_col + i;
            float v = (gr < M && gk < K) ? A[(size_t)gr * K + gk] : 0.f;
            As[a_col + i][a_row] = v;
        }
        // B tile: 8 k x 128 cols, vectorized when fully in-bounds
        {
            int gk = k0 + b_row;
            int gc = bn + b_col;
            if (gk < K && gc + 4 <= N) {
                float4 v = *(const float4*)(B + (size_t)gk * N + gc);
                *(float4*)&Bs[b_row][b_col] = v;
            } else {
#pragma unroll
                for (int i = 0; i < 4; i++)
                    Bs[b_row][b_col + i] =
                        (gk < K && gc + i < N) ? B[(size_t)gk * N + gc + i] : 0.f;
            }
        }
        __syncthreads();

#pragma unroll
        for (int kk = 0; kk < 8; kk++) {
            float a[8], b[8];
            *(float4*)(a)     = *(const float4*)&As[kk][ty * 8];
            *(float4*)(a + 4) = *(const float4*)&As[kk][ty * 8 + 4];
            *(float4*)(b)     = *(const float4*)&Bs[kk][tx * 8];
            *(float4*)(b + 4) = *(const float4*)&Bs[kk][tx * 8 + 4];
#pragma unroll
            for (int i = 0; i < 8; i++)
#pragma unroll
                for (int j = 0; j < 8; j++) acc[i][j] += a[i] * b[j];
        }
        __syncthreads();
    }

#pragma unroll
    for (int i = 0; i < 8; i++) {
        int r = bm + ty * 8 + i;
        if (r >= M) continue;
#pragma unroll
        for (int j = 0; j < 8; j++) {
            int c = bn + tx * 8 + j;
            if (c >= N) continue;
            float v = acc[i][j];
            if (EPI == 2) {
                v = v * scale[c] + bias[c];
            } else if (EPI == 1) {
                v += bias[c];
                v = v > 0.f ? v : 0.01f * v;
            }
            C[(size_t)r * N + c] = v;
        }
    }
}

// ---------------- launch ----------------
extern "C" void kernel_launch(void* const* d_in, const int* in_sizes, int n_in,
                              void* d_out_, int out_size) {
    const int*   d_index       = (const int*)d_in[0];
    const int*   p_index       = (const int*)d_in[1];
    const float* d_vecs        = (const float*)d_in[2];
    const float* p_embeddings  = (const float*)d_in[3];
    const float* d_ecfps       = (const float*)d_in[4];
    const int*   d_edge_index  = (const int*)d_in[5];
    const float* d_edge_weight = (const float*)d_in[6];
    const float* p_gos         = (const float*)d_in[7];
    const int*   p_edge_index  = (const int*)d_in[8];
    const float* p_edge_weight = (const float*)d_in[9];
    const float* d_gcn_W       = (const float*)d_in[10];
    const float* d_gcn_b       = (const float*)d_in[11];
    const float* p_gcn_W       = (const float*)d_in[12];
    const float* p_gcn_b       = (const float*)d_in[13];
    const float* enc_W1        = (const float*)d_in[14];
    const float* enc_b1        = (const float*)d_in[15];
    const float* enc_W2        = (const float*)d_in[16];
    const float* enc_b2        = (const float*)d_in[17];
    const float* dec_W1        = (const float*)d_in[18];
    const float* dec_b1        = (const float*)d_in[19];
    const float* dec_W2        = (const float*)d_in[20];
    const float* dec_b2        = (const float*)d_in[21];
    const float* out_W1        = (const float*)d_in[22];
    const float* out_b1        = (const float*)d_in[23];
    const float* bn_gamma      = (const float*)d_in[24];
    const float* bn_beta       = (const float*)d_in[25];
    const float* bn_mean       = (const float*)d_in[26];
    const float* bn_var        = (const float*)d_in[27];
    const float* out_W2        = (const float*)d_in[28];
    const float* out_b2        = (const float*)d_in[29];

    float* out      = (float*)d_out_;
    float* y_out    = out;                                   // [4096,1]
    float* enc_out  = out + NB;                              // [4096,256]
    float* dec_out  = enc_out + (size_t)NB * 256;            // [4096,3372]
    float* feat_out = dec_out + (size_t)NB * FEAT;           // [4096,3372]

    float *h_d, *h_p, *agg_d, *agg_p, *dinv_d, *dinv_p, *t1, *t2, *hbn;
    int *need_d, *need_p;
    cudaGetSymbolAddress((void**)&h_d,    g_h_d);
    cudaGetSymbolAddress((void**)&h_p,    g_h_p);
    cudaGetSymbolAddress((void**)&agg_d,  g_agg_d);
    cudaGetSymbolAddress((void**)&agg_p,  g_agg_p);
    cudaGetSymbolAddress((void**)&dinv_d, g_dinv_d);
    cudaGetSymbolAddress((void**)&dinv_p, g_dinv_p);
    cudaGetSymbolAddress((void**)&need_d, g_need_d);
    cudaGetSymbolAddress((void**)&need_p, g_need_p);
    cudaGetSymbolAddress((void**)&t1,     g_t1);
    cudaGetSymbolAddress((void**)&t2,     g_t2);
    cudaGetSymbolAddress((void**)&hbn,    g_hbn);
    float *bns, *bnb;
    cudaGetSymbolAddress((void**)&bns, g_bns);
    cudaGetSymbolAddress((void**)&bnb, g_bnb);

    // reset per-invocation state (graph replays must be deterministic)
    cudaMemsetAsync(dinv_d, 0, ND * sizeof(float));
    cudaMemsetAsync(dinv_p, 0, NP_ * sizeof(float));
    cudaMemsetAsync(need_d, 0, ND * sizeof(int));
    cudaMemsetAsync(need_p, 0, NP_ * sizeof(int));

    flag_kernel<<<(NB + 255) / 256, 256>>>(d_index, p_index);
    deg_kernel<<<(DE + 255) / 256, 256>>>(d_edge_index, d_edge_weight, dinv_d, DE);
    deg_kernel<<<(PE + 255) / 256, 256>>>(p_edge_index, p_edge_weight, dinv_p, PE);
    dinv_kernel<<<(ND + 255) / 256, 256>>>(dinv_d, ND);
    dinv_kernel<<<(NP_ + 255) / 256, 256>>>(dinv_p, NP_);

    // GCN feature transforms: h = X @ W
    sgemm<0><<<dim3(HID / 128, (ND + 127) / 128), 256>>>(
        d_ecfps, d_gcn_W, h_d, ND, HID, 1024, nullptr, nullptr);
    sgemm<0><<<dim3(HID / 128, (NP_ + 127) / 128), 256>>>(
        p_gos, p_gcn_W, h_p, NP_, HID, 2812, nullptr, nullptr);

    // aggregation: init with self loop term, then scatter edges (needed cols only)
    self_init<<<ND, 256>>>(h_d, agg_d, dinv_d, need_d);
    self_init<<<NP_, 256>>>(h_p, agg_p, dinv_p, need_p);
    edge_agg<<<DE, 256>>>(h_d, agg_d, dinv_d, need_d, d_edge_index, d_edge_weight, DE);
    edge_agg<<<PE, 256>>>(h_p, agg_p, dinv_p, need_p, p_edge_index, p_edge_weight, PE);

    // feature = concat(d_vecs, p_embeddings, leaky(gcn_d+b)[d_index], leaky(gcn_p+b)[p_index])
    feature_kernel<<<NB, 256>>>(d_index, p_index, d_vecs, p_embeddings,
                                d_gcn_b, p_gcn_b, feat_out);

    // encoder
    sgemm<1><<<dim3(HID / 128, NB / 128), 256>>>(
        feat_out, enc_W1, t1, NB, HID, FEAT, enc_b1, nullptr);
    sgemm<1><<<dim3(256 / 128, NB / 128), 256>>>(
        t1, enc_W2, enc_out, NB, 256, HID, enc_b2, nullptr);
    // decoder
    sgemm<1><<<dim3(HID / 128, NB / 128), 256>>>(
        enc_out, dec_W1, t2, NB, HID, 256, dec_b1, nullptr);
    sgemm<1><<<dim3((FEAT + 127) / 128, NB / 128), 256>>>(
        t2, dec_W2, dec_out, NB, FEAT, HID, dec_b2, nullptr);

    // output head: fold BN into scale/bias epilogue, then leaky+dot
    bnfold_kernel<<<1, 128>>>(out_b1, bn_gamma, bn_beta, bn_mean, bn_var);
    sgemm<2><<<dim3(1, NB / 128), 256>>>(
        enc_out, out_W1, hbn, NB, 128, 256, bnb, bns);
    y_kernel<<<NB / 8, 256>>>(out_W2, out_b2, y_out);
}